// round 2
// baseline (speedup 1.0000x reference)
#include <cuda_runtime.h>
#include <math.h>

#define BB 512
#define NXD 64
#define NYD 64
#define HID 256

// Scratch (allocation-free rule: __device__ globals)
__device__ float g_xp[BB * HID];       // Xp[j][k] = b1[k] + X[j]@W1[:64]
__device__ float g_yp[BB * HID];       // Yp[i][k] = Y[i]@W1[64:]
__device__ float g_scores[BB * BB];    // scores[i][j]
__device__ float g_lse[BB];

// ---------------------------------------------------------------------------
// Kernel A: factorized layer-1 projections
// ---------------------------------------------------------------------------
__global__ void proj_kernel(const float* __restrict__ X,
                            const float* __restrict__ Y,
                            const float* __restrict__ W1,
                            const float* __restrict__ b1) {
    int idx = blockIdx.x * blockDim.x + threadIdx.x;
    const int half = BB * HID;
    if (idx < half) {
        int r = idx / HID, k = idx % HID;
        float acc = b1[k];
        #pragma unroll 8
        for (int t = 0; t < NXD; t++)
            acc = fmaf(X[r * NXD + t], W1[t * HID + k], acc);
        g_xp[idx] = acc;
    } else {
        int e = idx - half;
        int r = e / HID, k = e % HID;
        float acc = 0.f;
        #pragma unroll 8
        for (int t = 0; t < NYD; t++)
            acc = fmaf(Y[r * NYD + t], W1[(NXD + t) * HID + k], acc);
        g_yp[e] = acc;
    }
}

// ---------------------------------------------------------------------------
// Kernel B: fused layer2 GEMM + layer3 dot per 64-pair tile
// Grid: (64, 64) tiles of (8 x-cols) x (8 y-rows). Block: 256 threads.
// smem: h1 tile [64][256] + W2 k-tile [64][256] + w3[256] + b2[256]
// ---------------------------------------------------------------------------
#define SMEM_FLOATS (64 * 256 * 2 + 512)
#define SMEM_BYTES (SMEM_FLOATS * 4)

extern __shared__ float s_dyn[];

__global__ void __launch_bounds__(256, 1)
mlp_kernel(const float* __restrict__ W2,
           const float* __restrict__ b2,
           const float* __restrict__ W3,
           const float* __restrict__ b3) {
    float* h1s = s_dyn;                 // 64*256
    float* w2s = s_dyn + 64 * 256;      // 64*256
    float* w3s = w2s + 64 * 256;        // 256
    float* b2s = w3s + 256;             // 256

    const int tid = threadIdx.x;
    const int tx = tid & 31;            // N dimension (lane)
    const int ty = tid >> 5;            // warp id -> row group
    const int bx = blockIdx.x;          // x-tile (j)
    const int by = blockIdx.y;          // y-tile (i)

    w3s[tid] = W3[tid];
    b2s[tid] = b2[tid];

    // Build h1 tile: pair p -> (ii = p>>3 local y, jj = p&7 local x)
    for (int e = tid; e < 64 * 256; e += 256) {
        int p = e >> 8, k = e & 255;
        int i = by * 8 + (p >> 3);
        int j = bx * 8 + (p & 7);
        float v = g_xp[j * HID + k] + g_yp[i * HID + k];
        h1s[e] = fmaxf(v, 0.f);
    }

    float acc[8][8];
    #pragma unroll
    for (int m = 0; m < 8; m++)
        #pragma unroll
        for (int n = 0; n < 8; n++) acc[m][n] = 0.f;

    for (int kt = 0; kt < HID; kt += 64) {
        __syncthreads();   // protect w2s from previous iteration readers; also fences h1s build
        for (int e = tid; e < 64 * 256; e += 256) {
            int kk = e >> 8, n = e & 255;
            w2s[e] = W2[(kt + kk) * HID + n];
        }
        __syncthreads();

        for (int k = 0; k < 64; k++) {
            float a[8], bv[8];
            #pragma unroll
            for (int m = 0; m < 8; m++)
                a[m] = h1s[(ty * 8 + m) * 256 + kt + k];
            #pragma unroll
            for (int n = 0; n < 8; n++)
                bv[n] = w2s[k * 256 + tx + n * 32];
            #pragma unroll
            for (int m = 0; m < 8; m++)
                #pragma unroll
                for (int n = 0; n < 8; n++)
                    acc[m][n] = fmaf(a[m], bv[n], acc[m][n]);
        }
    }

    // Epilogue: relu(h2) @ W3, warp reduce over N (lanes), write scores
    const float b3v = b3[0];
    #pragma unroll
    for (int m = 0; m < 8; m++) {
        float part = 0.f;
        #pragma unroll
        for (int n = 0; n < 8; n++) {
            int c = tx + n * 32;
            float h = fmaxf(acc[m][n] + b2s[c], 0.f);
            part = fmaf(h, w3s[c], part);
        }
        #pragma unroll
        for (int off = 16; off; off >>= 1)
            part += __shfl_xor_sync(0xffffffffu, part, off);
        if (tx == 0) {
            int row = ty * 8 + m;
            int i = by * 8 + (row >> 3);
            int j = bx * 8 + (row & 7);
            g_scores[i * BB + j] = part + b3v;
        }
    }
}

// ---------------------------------------------------------------------------
// Kernel C1: per-row logsumexp
// ---------------------------------------------------------------------------
__global__ void lse_kernel() {
    __shared__ float red[256];
    const int row = blockIdx.x;
    const int tid = threadIdx.x;
    const float* s = g_scores + row * BB;

    float mx = -INFINITY;
    for (int c = tid; c < BB; c += 256) mx = fmaxf(mx, s[c]);
    red[tid] = mx;
    __syncthreads();
    for (int o = 128; o; o >>= 1) {
        if (tid < o) red[tid] = fmaxf(red[tid], red[tid + o]);
        __syncthreads();
    }
    mx = red[0];
    __syncthreads();

    float sum = 0.f;
    for (int c = tid; c < BB; c += 256) sum += expf(s[c] - mx);
    red[tid] = sum;
    __syncthreads();
    for (int o = 128; o; o >>= 1) {
        if (tid < o) red[tid] += red[tid + o];
        __syncthreads();
    }
    if (tid == 0) g_lse[row] = mx + logf(red[0]);
}

// ---------------------------------------------------------------------------
// Kernel C2: final scalar
// ---------------------------------------------------------------------------
__global__ void final_kernel(float* __restrict__ out) {
    __shared__ float rd[512];
    __shared__ float rl[512];
    const int t = threadIdx.x;
    rd[t] = g_scores[t * BB + t];
    rl[t] = g_lse[t];
    __syncthreads();
    for (int o = 256; o; o >>= 1) {
        if (t < o) { rd[t] += rd[t + o]; rl[t] += rl[t + o]; }
        __syncthreads();
    }
    if (t == 0) {
        float mi = logf((float)BB) + rd[0] / (float)BB - rl[0] / (float)BB;
        out[0] = -mi;
    }
}

// ---------------------------------------------------------------------------
extern "C" void kernel_launch(void* const* d_in, const int* in_sizes, int n_in,
                              void* d_out, int out_size) {
    const float* dataX = (const float*)d_in[0];
    const float* dataY = (const float*)d_in[1];
    const float* W1    = (const float*)d_in[2];
    const float* b1    = (const float*)d_in[3];
    const float* W2    = (const float*)d_in[4];
    const float* b2    = (const float*)d_in[5];
    const float* W3    = (const float*)d_in[6];
    const float* b3    = (const float*)d_in[7];
    float* out = (float*)d_out;

    cudaFuncSetAttribute(mlp_kernel, cudaFuncAttributeMaxDynamicSharedMemorySize,
                         SMEM_BYTES);

    proj_kernel<<<(2 * BB * HID) / 256, 256>>>(dataX, dataY, W1, b1);

    dim3 grid(BB / 8, BB / 8);
    mlp_kernel<<<grid, 256, SMEM_BYTES>>>(W2, b2, W3, b3);

    lse_kernel<<<BB, 256>>>();
    final_kernel<<<1, BB>>>(out);
}

// round 5
// speedup vs baseline: 3.8999x; 3.8999x over previous
#include <cuda_runtime.h>
#include <cuda_bf16.h>
#include <math.h>
#include <stdint.h>

#define BB 512
#define NXD 64
#define NYD 64
#define HID 256

// ---------------- device scratch ---------------------------------------------
__device__ float    g_xp[BB * HID];        // b1 + X@W1[:64]
__device__ float    g_yp[BB * HID];        // Y@W1[64:]
__device__ uint32_t g_w2hi[HID * 128];     // W2^T hi bf16 pairs: [n][kp] kp=k/2
__device__ uint32_t g_w2lo[HID * 128];     // W2^T lo bf16 pairs
__device__ float    g_scores[BB * BB];
__device__ float    g_lse[BB];

// ---------------- helpers ----------------------------------------------------
__device__ __forceinline__ uint32_t smem_u32(const void* p) {
    uint32_t a;
    asm("{ .reg .u64 t; cvta.to.shared.u64 t, %1; cvt.u32.u64 %0, t; }"
        : "=r"(a) : "l"(p));
    return a;
}

__device__ __forceinline__ void split_pack(float v0, float v1,
                                           uint32_t& hi, uint32_t& lo) {
    __nv_bfloat162 h = __float22bfloat162_rn(make_float2(v0, v1));
    float2 hf = __bfloat1622float2(h);
    __nv_bfloat162 l = __float22bfloat162_rn(make_float2(v0 - hf.x, v1 - hf.y));
    hi = *reinterpret_cast<uint32_t*>(&h);
    lo = *reinterpret_cast<uint32_t*>(&l);
}

__device__ __forceinline__ void mma_bf16(float* c, const uint32_t* a,
                                         const uint32_t* b) {
    asm volatile(
        "mma.sync.aligned.m16n8k16.row.col.f32.bf16.bf16.f32 "
        "{%0,%1,%2,%3}, {%4,%5,%6,%7}, {%8,%9}, {%0,%1,%2,%3};"
        : "+f"(c[0]), "+f"(c[1]), "+f"(c[2]), "+f"(c[3])
        : "r"(a[0]), "r"(a[1]), "r"(a[2]), "r"(a[3]), "r"(b[0]), "r"(b[1]));
}

__device__ __forceinline__ void cpa16(uint32_t dst, const void* src) {
    asm volatile("cp.async.cg.shared.global [%0], [%1], 16;"
                 :: "r"(dst), "l"(__cvta_generic_to_global(src)) : "memory");
}

// ---------------------------------------------------------------------------
// Kernel A: factorized layer-1 projections (fp32)
// ---------------------------------------------------------------------------
__global__ void proj_kernel(const float* __restrict__ X,
                            const float* __restrict__ Y,
                            const float* __restrict__ W1,
                            const float* __restrict__ b1) {
    int idx = blockIdx.x * blockDim.x + threadIdx.x;
    const int half = BB * HID;
    if (idx < half) {
        int r = idx / HID, k = idx % HID;
        float acc = b1[k];
        #pragma unroll 8
        for (int t = 0; t < NXD; t++)
            acc = fmaf(X[r * NXD + t], W1[t * HID + k], acc);
        g_xp[idx] = acc;
    } else {
        int e = idx - half;
        int r = e / HID, k = e % HID;
        float acc = 0.f;
        #pragma unroll 8
        for (int t = 0; t < NYD; t++)
            acc = fmaf(Y[r * NYD + t], W1[(NXD + t) * HID + k], acc);
        g_yp[e] = acc;
    }
}

// ---------------------------------------------------------------------------
// Kernel A2: W2^T -> packed bf16 hi/lo pairs. g_w2hi[n*128+kp] = pack(W2[2kp][n], W2[2kp+1][n])
// ---------------------------------------------------------------------------
__global__ void prep_w2(const float* __restrict__ W2) {
    int idx = blockIdx.x * blockDim.x + threadIdx.x;  // 32768
    int n = idx >> 7, kp = idx & 127;
    float w0 = W2[(2 * kp) * HID + n];
    float w1 = W2[(2 * kp + 1) * HID + n];
    uint32_t hi, lo;
    split_pack(w0, w1, hi, lo);
    g_w2hi[idx] = hi;
    g_w2lo[idx] = lo;
}

// ---------------------------------------------------------------------------
// Kernel B: mma.sync bf16 3-split GEMM + fused epilogue.
// CTA: 128 pairs (16 y x 8 x), N=256 in two halves of 128, K=256.
// smem (uint32 units):
//   A_HI [0,16896)      128 rows x 128 kp, stride 132
//   A_LO [16896,33792)
//   B    [33792,44032)  2 bufs x (hi 2560 + lo 2560), 128 cols x 16 kp, stride 20
//   B2S  [44032,44288)  W3S [44288,44544)  PART [44544,44800)
// ---------------------------------------------------------------------------
#define SA   132
#define SB   20
#define A_HI 0
#define A_LO 16896
#define B_BASE 33792
#define B2S  44032
#define W3S  44288
#define PART 44544
#define SM_U32 44800
#define SM_BYTES (SM_U32 * 4)

__global__ void __launch_bounds__(256, 1)
mlp_mma_kernel(const float* __restrict__ b2,
               const float* __restrict__ W3,
               const float* __restrict__ b3) {
    extern __shared__ __align__(16) uint32_t sm[];
    const int tid = threadIdx.x;
    const int lane = tid & 31, wid = tid >> 5;
    const int lq = lane >> 2, lr = lane & 3;
    const int wm = wid >> 1, wn = wid & 1;
    const int i0 = blockIdx.y * 16, j0 = blockIdx.x * 8;
    const uint32_t sb = smem_u32(sm);

    ((float*)(sm + B2S))[tid] = b2[tid];
    ((float*)(sm + W3S))[tid] = W3[tid];

    // ---- build A = relu(xp[j]+yp[i]) split to bf16 hi/lo pairs -------------
    #pragma unroll 4
    for (int q = 0; q < 32; q++) {
        int e = tid + q * 256;              // (row, kp2) : kp2 = 4-float group
        int row = e >> 6, kp2 = e & 63;
        int i = i0 + (row >> 3), j = j0 + (row & 7);
        float4 xv = *(const float4*)(g_xp + j * HID + kp2 * 4);
        float4 yv = *(const float4*)(g_yp + i * HID + kp2 * 4);
        float v0 = fmaxf(xv.x + yv.x, 0.f), v1 = fmaxf(xv.y + yv.y, 0.f);
        float v2 = fmaxf(xv.z + yv.z, 0.f), v3 = fmaxf(xv.w + yv.w, 0.f);
        uint32_t h0, l0, h1, l1;
        split_pack(v0, v1, h0, l0);
        split_pack(v2, v3, h1, l1);
        int a = row * SA + kp2 * 2;
        sm[A_HI + a] = h0; sm[A_HI + a + 1] = h1;
        sm[A_LO + a] = l0; sm[A_LO + a + 1] = l1;
    }

    // ---- B pipeline: 16 chunks (nh 0..1 x kc 0..7), k=32 each --------------
    auto load_chunk = [&](int t, int buf) {
        int nh = t >> 3, kc = t & 7;
        uint32_t bbase = B_BASE + buf * 5120;
        #pragma unroll
        for (int q = 0; q < 4; q++) {
            int idx = tid + q * 256;        // 1024: [half(hi/lo)][n_local][jj]
            int hl = idx >> 9;
            int nl = (idx & 511) >> 2, jj = idx & 3;
            const uint32_t* src = (hl ? g_w2lo : g_w2hi)
                                  + (nh * 128 + nl) * 128 + kc * 16 + jj * 4;
            uint32_t dst = sb + (bbase + hl * 2560 + nl * SB + jj * 4) * 4;
            cpa16(dst, src);
        }
        asm volatile("cp.async.commit_group;" ::: "memory");
    };

    load_chunk(0, 0);

    float c[2][8][4];
    #pragma unroll
    for (int mt = 0; mt < 2; mt++)
        #pragma unroll
        for (int nt = 0; nt < 8; nt++)
            #pragma unroll
            for (int q = 0; q < 4; q++) c[mt][nt][q] = 0.f;

    float pr[2][2] = {{0.f, 0.f}, {0.f, 0.f}};
    const float* b2s = (const float*)(sm + B2S);
    const float* w3s = (const float*)(sm + W3S);

    for (int t = 0; t < 16; t++) {
        const int buf = t & 1;
        const int nh = t >> 3, kc = t & 7;
        if (t < 15) {
            load_chunk(t + 1, buf ^ 1);
            asm volatile("cp.async.wait_group 1;" ::: "memory");
        } else {
            asm volatile("cp.async.wait_group 0;" ::: "memory");
        }
        __syncthreads();

        const uint32_t* Bh = sm + B_BASE + buf * 5120;
        const uint32_t* Bl = Bh + 2560;

        #pragma unroll
        for (int s = 0; s < 2; s++) {       // two k16 steps per chunk
            const int kpb = kc * 16 + s * 8;
            uint32_t ah[2][4], al[2][4];
            #pragma unroll
            for (int mt = 0; mt < 2; mt++) {
                int a = (wm * 32 + mt * 16 + lq) * SA + kpb + lr;
                ah[mt][0] = sm[A_HI + a];            al[mt][0] = sm[A_LO + a];
                ah[mt][1] = sm[A_HI + a + 8 * SA];   al[mt][1] = sm[A_LO + a + 8 * SA];
                ah[mt][2] = sm[A_HI + a + 4];        al[mt][2] = sm[A_LO + a + 4];
                ah[mt][3] = sm[A_HI + a + 8 * SA + 4]; al[mt][3] = sm[A_LO + a + 8 * SA + 4];
            }
            #pragma unroll
            for (int nt = 0; nt < 8; nt++) {
                int bidx = (wn * 64 + nt * 8 + lq) * SB + s * 8 + lr;
                uint32_t bh[2], bl[2];
                bh[0] = Bh[bidx]; bh[1] = Bh[bidx + 4];
                bl[0] = Bl[bidx]; bl[1] = Bl[bidx + 4];
                #pragma unroll
                for (int mt = 0; mt < 2; mt++) {
                    mma_bf16(c[mt][nt], ah[mt], bh);
                    mma_bf16(c[mt][nt], ah[mt], bl);
                    mma_bf16(c[mt][nt], al[mt], bh);
                }
            }
        }

        if (kc == 7) {                       // half done -> partial epilogue
            #pragma unroll
            for (int mt = 0; mt < 2; mt++)
                #pragma unroll
                for (int nt = 0; nt < 8; nt++)
                    #pragma unroll
                    for (int q = 0; q < 4; q++) {
                        int col = nh * 128 + wn * 64 + nt * 8 + lr * 2 + (q & 1);
                        float h = fmaxf(c[mt][nt][q] + b2s[col], 0.f);
                        pr[mt][q >> 1] = fmaf(h, w3s[col], pr[mt][q >> 1]);
                        c[mt][nt][q] = 0.f;
                    }
        }
        __syncthreads();
    }

    // ---- reduce partial dots over lane%4 group, combine warps --------------
    #pragma unroll
    for (int mt = 0; mt < 2; mt++)
        #pragma unroll
        for (int rh = 0; rh < 2; rh++) {
            float p = pr[mt][rh];
            p += __shfl_xor_sync(0xffffffffu, p, 1);
            p += __shfl_xor_sync(0xffffffffu, p, 2);
            if (lr == 0) {
                int row = wm * 32 + mt * 16 + rh * 8 + lq;
                ((float*)(sm + PART))[row * 2 + wn] = p;
            }
        }
    __syncthreads();

    if (tid < 128) {
        const float* part = (const float*)(sm + PART);
        float sc = part[tid * 2] + part[tid * 2 + 1] + b3[0];
        int i = i0 + (tid >> 3), j = j0 + (tid & 7);
        g_scores[i * BB + j] = sc;
    }
}

// ---------------------------------------------------------------------------
// Kernel C1: per-row logsumexp
// ---------------------------------------------------------------------------
__global__ void lse_kernel() {
    __shared__ float red[256];
    const int row = blockIdx.x;
    const int tid = threadIdx.x;
    const float* s = g_scores + row * BB;

    float mx = -INFINITY;
    for (int cc = tid; cc < BB; cc += 256) mx = fmaxf(mx, s[cc]);
    red[tid] = mx;
    __syncthreads();
    for (int o = 128; o; o >>= 1) {
        if (tid < o) red[tid] = fmaxf(red[tid], red[tid + o]);
        __syncthreads();
    }
    mx = red[0];
    __syncthreads();

    float sum = 0.f;
    for (int cc = tid; cc < BB; cc += 256) sum += expf(s[cc] - mx);
    red[tid] = sum;
    __syncthreads();
    for (int o = 128; o; o >>= 1) {
        if (tid < o) red[tid] += red[tid + o];
        __syncthreads();
    }
    if (tid == 0) g_lse[row] = mx + logf(red[0]);
}

// ---------------------------------------------------------------------------
// Kernel C2: final scalar
// ---------------------------------------------------------------------------
__global__ void final_kernel(float* __restrict__ out) {
    __shared__ float rd[512];
    __shared__ float rl[512];
    const int t = threadIdx.x;
    rd[t] = g_scores[t * BB + t];
    rl[t] = g_lse[t];
    __syncthreads();
    for (int o = 256; o; o >>= 1) {
        if (t < o) { rd[t] += rd[t + o]; rl[t] += rl[t + o]; }
        __syncthreads();
    }
    if (t == 0) {
        float mi = logf((float)BB) + rd[0] / (float)BB - rl[0] / (float)BB;
        out[0] = -mi;
    }
}

// ---------------------------------------------------------------------------
extern "C" void kernel_launch(void* const* d_in, const int* in_sizes, int n_in,
                              void* d_out, int out_size) {
    const float* dataX = (const float*)d_in[0];
    const float* dataY = (const float*)d_in[1];
    const float* W1    = (const float*)d_in[2];
    const float* b1    = (const float*)d_in[3];
    const float* W2    = (const float*)d_in[4];
    const float* b2    = (const float*)d_in[5];
    const float* W3    = (const float*)d_in[6];
    const float* b3    = (const float*)d_in[7];
    float* out = (float*)d_out;

    cudaFuncSetAttribute(mlp_mma_kernel,
                         cudaFuncAttributeMaxDynamicSharedMemorySize, SM_BYTES);

    proj_kernel<<<(2 * BB * HID) / 256, 256>>>(dataX, dataY, W1, b1);
    prep_w2<<<(HID * 128) / 256, 256>>>(W2);

    dim3 grid(BB / 8, BB / 16);   // 64 x-tiles x 32 y-tiles
    mlp_mma_kernel<<<grid, 256, SM_BYTES>>>(b2, W3, b3);

    lse_kernel<<<BB, 256>>>();
    final_kernel<<<1, BB>>>(out);
}